// round 11
// baseline (speedup 1.0000x reference)
#include <cuda_runtime.h>
#include <cuda_bf16.h>
#include <math.h>

#define BSZ   4096
#define TSZ   1024
#define DIN   2
#define EMD   128
#define CELL  128
#define DOUT  5
#define GATES 512
#define NCTA  128
#define ROWS  32
#define NTHR  512
#define STR   136            /* A-plane row stride (bf16) */
#define HSST  132
#define WOST  132
#define NBF   (16*16*4*32*8) /* 512KB: [kt][w][nt][lane][hi x4 | lo x4] */
#define CHUNK 128            /* timesteps per chunk */
#define NCHUNK (TSZ / CHUNK)

typedef unsigned int u32;

/* ---------------- persistent device scratch (total < 1.1 GiB, links OK) ---------------- */
__device__ __nv_bfloat16 g_B[NBF];
__device__ float g_bias[GATES];
/* gates_e chunk: [t%128][ctab][j=mt*4+nt][tid] float4 = 1 GiB */
#define GF4 (128UL * NCTA * 8 * 512)
__device__ float4 g_G[GF4];
/* h/c state carried across chunk launches */
__device__ float g_hf[BSZ * CELL];
__device__ float g_cf[BSZ * CELL];

__device__ __forceinline__ float4* gchunk(int t, int ctab) {
    return g_G + ((size_t)(t & (CHUNK - 1)) * NCTA + ctab) * 4096;
}

/* ---------------- helpers ---------------- */
__device__ __forceinline__ float sigm(float x) {
    return __fdividef(1.0f, 1.0f + __expf(-x));
}
__device__ __forceinline__ float tanh_f(float x) {
    float e = __expf(-2.0f * fabsf(x));
    float r = __fdividef(1.0f - e, 1.0f + e);
    return copysignf(r, x);
}
__device__ __forceinline__ void mma16816(float* d, const u32* a, u32 b0, u32 b1) {
    asm("mma.sync.aligned.m16n8k16.row.col.f32.bf16.bf16.f32 "
        "{%0,%1,%2,%3}, {%4,%5,%6,%7}, {%8,%9}, {%0,%1,%2,%3};"
        : "+f"(d[0]), "+f"(d[1]), "+f"(d[2]), "+f"(d[3])
        : "r"(a[0]), "r"(a[1]), "r"(a[2]), "r"(a[3]), "r"(b0), "r"(b1));
}
__device__ __forceinline__ void ldmat4(u32* r, u32 addr) {
    asm volatile("ldmatrix.sync.aligned.m8n8.x4.shared.b16 {%0,%1,%2,%3}, [%4];"
        : "=r"(r[0]), "=r"(r[1]), "=r"(r[2]), "=r"(r[3]) : "r"(addr));
}
__device__ __forceinline__ void cp16(void* s, const void* g) {
    unsigned sa = (unsigned)__cvta_generic_to_shared(s);
    asm volatile("cp.async.cg.shared.global [%0], [%1], 16;" :: "r"(sa), "l"(g));
}
__device__ __forceinline__ void cp_commit() { asm volatile("cp.async.commit_group;"); }
__device__ __forceinline__ void cp_wait0()  { asm volatile("cp.async.wait_group 0;" ::: "memory"); }

/* ---------------- setup: bf16 hi/lo split weights + zero h/c state ---------------- */
__global__ void setup_kernel(const float* __restrict__ W_ih, const float* __restrict__ W_hh,
                             const float* __restrict__ b_ih, const float* __restrict__ b_hh) {
    int idx = blockIdx.x * blockDim.x + threadIdx.x;
    if (idx < NBF) {
        int j  = idx & 3;
        int p  = (idx >> 2) & 1;
        int l  = (idx >> 3) & 31;
        int nt = (idx >> 8) & 3;
        int w  = (idx >> 10) & 15;
        int kt = idx >> 14;
        int k  = kt * 16 + 2 * (l & 3) + (j & 1) + 8 * (j >> 1);
        int n  = nt * 128 + 8 * w + (l >> 2);
        float v = (k < EMD) ? W_ih[n * EMD + k] : W_hh[n * CELL + (k - EMD)];
        __nv_bfloat16 hi = __float2bfloat16_rn(v);
        g_B[idx] = p ? __float2bfloat16_rn(v - __bfloat162float(hi)) : hi;
    }
    if (idx < GATES) g_bias[idx] = b_ih[idx] + b_hh[idx];
    if (idx < BSZ * CELL) { g_hf[idx] = 0.0f; g_cf[idx] = 0.0f; }
}

/* ---------------- pre-pass: gates_e for one 128-step chunk ----------------
 * grid 512: ctab = bx & 127, tc = bx >> 7 (32 timesteps per CTA). */
__global__ void __launch_bounds__(NTHR, 1)
prepass_kernel(const float* __restrict__ inputs,
               const float* __restrict__ We, const float* __restrict__ be, int ci) {
    __shared__ __nv_bfloat16 AeHi[ROWS * STR];
    __shared__ __nv_bfloat16 AeLo[ROWS * STR];
    __shared__ float2 xsh[ROWS * 32];
    __shared__ float  WeS[2 * EMD];
    __shared__ float  beS[EMD];

    const int tid  = threadIdx.x;
    const int ctab = blockIdx.x & 127;
    const int tc   = blockIdx.x >> 7;
    const int row0 = ctab * ROWS;
    const int t0   = ci * CHUNK + tc * 32;
    const int w    = tid >> 5;
    const int l    = tid & 31;

    for (int i = tid; i < EMD; i += NTHR) {
        WeS[2 * i] = We[2 * i]; WeS[2 * i + 1] = We[2 * i + 1]; beS[i] = be[i];
    }
    for (int i = tid; i < ROWS * 32; i += NTHR) {
        int r = i >> 5, tt = i & 31;
        xsh[i] = ((const float2*)inputs)[(size_t)(row0 + r) * TSZ + t0 + tt];
    }

    float bia[4][2];
    {
        const int cp = l & 3, cell0 = 8 * w + 2 * cp;
#pragma unroll
        for (int nt = 0; nt < 4; nt++) {
            bia[nt][0] = g_bias[nt * 128 + cell0];
            bia[nt][1] = g_bias[nt * 128 + cell0 + 1];
        }
    }

    const int rl = (l & 7) + ((l >> 3) & 1) * 8;
    const int kl = (l >> 4) * 8;
    const u32 hiB0 = (u32)__cvta_generic_to_shared(AeHi) + (u32)((rl * STR + kl) * 2);
    const u32 loB0 = (u32)__cvta_generic_to_shared(AeLo) + (u32)((rl * STR + kl) * 2);

    const int ej  = tid >> 2;
    const int er0 = (tid & 3) * 8;
    const uint4* Bp = (const uint4*)g_B;
    const u32 bbase = w * 128 + l;

    __syncthreads();

    for (int tt = 0; tt < 32; tt++) {
        {
            float w0 = WeS[2 * ej], w1 = WeS[2 * ej + 1], bj = beS[ej];
#pragma unroll
            for (int i = 0; i < 8; i++) {
                int r = er0 + i;
                float2 x = xsh[r * 32 + tt];
                float e = fmaxf(fmaf(w0, x.x, fmaf(w1, x.y, bj)), 0.0f);
                __nv_bfloat16 hi = __float2bfloat16_rn(e);
                AeHi[r * STR + ej] = hi;
                AeLo[r * STR + ej] = __float2bfloat16_rn(e - __bfloat162float(hi));
            }
        }
        __syncthreads();

        float D[2][4][4];
#pragma unroll
        for (int mt = 0; mt < 2; mt++)
#pragma unroll
            for (int nt = 0; nt < 4; nt++) {
                D[mt][nt][0] = bia[nt][0]; D[mt][nt][1] = bia[nt][1];
                D[mt][nt][2] = bia[nt][0]; D[mt][nt][3] = bia[nt][1];
            }

        uint4 Bv[2][4];
#pragma unroll
        for (int nt = 0; nt < 4; nt++) Bv[0][nt] = __ldg(Bp + bbase + nt * 32);
#pragma unroll
        for (int kt = 0; kt < 8; kt++) {
            const int cur = kt & 1;
            if (kt < 7) {
#pragma unroll
                for (int nt = 0; nt < 4; nt++)
                    Bv[cur ^ 1][nt] = __ldg(Bp + (kt + 1) * 2048 + bbase + nt * 32);
            }
#pragma unroll
            for (int mt = 0; mt < 2; mt++) {
                u32 Ah[4], Al[4];
                ldmat4(Ah, hiB0 + kt * 32 + mt * (16 * STR * 2));
                ldmat4(Al, loB0 + kt * 32 + mt * (16 * STR * 2));
#pragma unroll
                for (int nt = 0; nt < 4; nt++)
                    mma16816(D[mt][nt], Ah, Bv[cur][nt].x, Bv[cur][nt].y);
#pragma unroll
                for (int nt = 0; nt < 4; nt++)
                    mma16816(D[mt][nt], Ah, Bv[cur][nt].z, Bv[cur][nt].w);
#pragma unroll
                for (int nt = 0; nt < 4; nt++)
                    mma16816(D[mt][nt], Al, Bv[cur][nt].x, Bv[cur][nt].y);
            }
        }

        float4* gp = gchunk(t0 + tt, ctab) + tid;
#pragma unroll
        for (int mt = 0; mt < 2; mt++)
#pragma unroll
            for (int nt = 0; nt < 4; nt++)
                gp[(mt * 4 + nt) * 512] =
                    make_float4(D[mt][nt][0], D[mt][nt][1], D[mt][nt][2], D[mt][nt][3]);

        __syncthreads();
    }
}

/* ---------------- main chunk kernel smem layout (bytes) ---------------- */
#define OFF_AHHI  0
#define OFF_AHLO  8704
#define OFF_HS    17408
#define OFF_WOS   34304
#define OFF_G0    36944
#define OFF_G1    102480
#define SMEM_BYTES 168016

__global__ void __launch_bounds__(NTHR, 1)
lstm_chunk(const float* __restrict__ Wo, const float* __restrict__ bov,
           float* __restrict__ out, int ci) {
    extern __shared__ char smc[];
    __nv_bfloat16* AhHi = (__nv_bfloat16*)(smc + OFF_AHHI);
    __nv_bfloat16* AhLo = (__nv_bfloat16*)(smc + OFF_AHLO);
    float*  Hs  = (float*)(smc + OFF_HS);
    float*  WoS = (float*)(smc + OFF_WOS);
    float4* Gs0 = (float4*)(smc + OFF_G0);
    float4* Gs1 = (float4*)(smc + OFF_G1);

    const int tid  = threadIdx.x;
    const int ctab = blockIdx.x;
    const int row0 = ctab * ROWS;
    const int w    = tid >> 5;
    const int l    = tid & 31;
    const int r0   = l >> 2;
    const int cp   = l & 3;
    const int cell0 = 8 * w + 2 * cp;

    const int rl = (l & 7) + ((l >> 3) & 1) * 8;
    const int kl = (l >> 4) * 8;
    const u32 sb = (u32)__cvta_generic_to_shared(smc);
    const u32 aoff = (u32)((rl * STR + kl) * 2);
    const u32 hHiB = sb + OFF_AHHI + aoff;
    const u32 hLoB = sb + OFF_AHLO + aoff;

    for (int i = tid; i < DOUT * CELL; i += NTHR) WoS[(i / CELL) * WOST + (i % CELL)] = Wo[i];
    /* rebuild h planes from carried state */
    for (int i = tid; i < ROWS * CELL; i += NTHR) {
        int r = i >> 7, c = i & 127;
        float h = g_hf[(row0 + r) * CELL + c];
        __nv_bfloat16 hb = __float2bfloat16_rn(h);
        AhHi[r * STR + c] = hb;
        AhLo[r * STR + c] = __float2bfloat16_rn(h - __bfloat162float(hb));
    }
    /* carried c state into registers */
    float cst[8];
#pragma unroll
    for (int mt = 0; mt < 2; mt++)
#pragma unroll
        for (int half = 0; half < 2; half++) {
            int r = mt * 16 + r0 + 8 * half;
            cst[mt * 4 + half * 2]     = g_cf[(row0 + r) * CELL + cell0];
            cst[mt * 4 + half * 2 + 1] = g_cf[(row0 + r) * CELL + cell0 + 1];
        }

    const float bo_r = (tid < ROWS * DOUT * 2) ? bov[(tid % 10) >> 1] : 0.0f;
    const uint4* Bp = (const uint4*)g_B;
    const u32 bbase = w * 128 + l;

    /* prologue: G(first step) into Gs0 */
    {
        const float4* src = gchunk(ci * CHUNK, ctab);
#pragma unroll
        for (int i = 0; i < 8; i++) cp16(Gs0 + tid + i * 512, src + tid + i * 512);
        cp_commit();
        cp_wait0();
    }
    __syncthreads();

    float hv[8];
    for (int tt = 0; tt < CHUNK; tt++) {
        const int t = ci * CHUNK + tt;
        float D[2][4][4];
        {
            const float4* Gc = (tt & 1) ? Gs1 : Gs0;
#pragma unroll
            for (int mt = 0; mt < 2; mt++)
#pragma unroll
                for (int nt = 0; nt < 4; nt++) {
                    float4 v = Gc[(mt * 4 + nt) * 512 + tid];
                    D[mt][nt][0] = v.x; D[mt][nt][1] = v.y;
                    D[mt][nt][2] = v.z; D[mt][nt][3] = v.w;
                }
        }
        if (tt < CHUNK - 1) {
            float4* dst = (tt & 1) ? Gs0 : Gs1;
            const float4* src = gchunk(t + 1, ctab);
#pragma unroll
            for (int i = 0; i < 8; i++) cp16(dst + tid + i * 512, src + tid + i * 512);
            cp_commit();
        }

        /* recurrent GEMM: K=128 over h-planes (B kt 8..15) */
        uint4 Bv[2][4];
#pragma unroll
        for (int nt = 0; nt < 4; nt++) Bv[0][nt] = __ldg(Bp + 8 * 2048 + bbase + nt * 32);
#pragma unroll
        for (int kt = 0; kt < 8; kt++) {
            const int cur = kt & 1;
            if (kt < 7) {
#pragma unroll
                for (int nt = 0; nt < 4; nt++)
                    Bv[cur ^ 1][nt] = __ldg(Bp + (kt + 9) * 2048 + bbase + nt * 32);
            }
#pragma unroll
            for (int mt = 0; mt < 2; mt++) {
                u32 Ah[4], Al[4];
                ldmat4(Ah, hHiB + kt * 32 + mt * (16 * STR * 2));
                ldmat4(Al, hLoB + kt * 32 + mt * (16 * STR * 2));
#pragma unroll
                for (int nt = 0; nt < 4; nt++)
                    mma16816(D[mt][nt], Ah, Bv[cur][nt].x, Bv[cur][nt].y);
#pragma unroll
                for (int nt = 0; nt < 4; nt++)
                    mma16816(D[mt][nt], Ah, Bv[cur][nt].z, Bv[cur][nt].w);
#pragma unroll
                for (int nt = 0; nt < 4; nt++)
                    mma16816(D[mt][nt], Al, Bv[cur][nt].x, Bv[cur][nt].y);
            }
        }

        /* pointwise in registers */
#pragma unroll
        for (int mt = 0; mt < 2; mt++)
#pragma unroll
            for (int half = 0; half < 2; half++)
#pragma unroll
                for (int cc = 0; cc < 2; cc++) {
                    const int e = 2 * half + cc;
                    float iv = sigm(D[mt][0][e]);
                    float fv = sigm(D[mt][1][e]);
                    float gv = tanh_f(D[mt][2][e]);
                    float ov = sigm(D[mt][3][e]);
                    const int cidx = mt * 4 + half * 2 + cc;
                    cst[cidx] = fmaf(fv, cst[cidx], iv * gv);
                    hv[cidx] = ov * tanh_f(cst[cidx]);
                }

        __syncthreads();   /* all GEMM reads of Ah done */

#pragma unroll
        for (int mt = 0; mt < 2; mt++)
#pragma unroll
            for (int half = 0; half < 2; half++) {
                const int r = mt * 16 + r0 + 8 * half;
                const int cidx = mt * 4 + half * 2;
                float h0 = hv[cidx], h1 = hv[cidx + 1];
                *(float2*)&Hs[r * HSST + cell0] = make_float2(h0, h1);
                __nv_bfloat16 b0 = __float2bfloat16_rn(h0);
                __nv_bfloat16 b1 = __float2bfloat16_rn(h1);
                *(__nv_bfloat162*)&AhHi[r * STR + cell0] = __nv_bfloat162(b0, b1);
                *(__nv_bfloat162*)&AhLo[r * STR + cell0] = __nv_bfloat162(
                    __float2bfloat16_rn(h0 - __bfloat162float(b0)),
                    __float2bfloat16_rn(h1 - __bfloat162float(b1)));
            }

        cp_wait0();
        __syncthreads();   /* h planes + G(t+1) visible */

        /* y-phase (overlaps next step's GEMM on other warps) */
        if (tid < ROWS * DOUT * 2) {
            int r = tid / 10, q = tid % 10;
            int d = q >> 1, half = q & 1;
            const float* hrow = Hs + r * HSST + 64 * half;
            const float* wrow = WoS + d * WOST + 64 * half;
            float s = 0.0f;
#pragma unroll 16
            for (int j = 0; j < 64; j++) s = fmaf(hrow[j], wrow[j], s);
            s += __shfl_xor_sync(0xffffffffu, s, 1);
            if (!half)
                out[((size_t)(row0 + r) * TSZ + t) * DOUT + d] = s + bo_r;
        }
    }

    /* chunk epilogue: persist h/c state */
#pragma unroll
    for (int mt = 0; mt < 2; mt++)
#pragma unroll
        for (int half = 0; half < 2; half++) {
            int r = mt * 16 + r0 + 8 * half;
            int cidx = mt * 4 + half * 2;
            *(float2*)&g_cf[(row0 + r) * CELL + cell0] = make_float2(cst[cidx], cst[cidx + 1]);
        }
    for (int i = tid; i < ROWS * CELL; i += NTHR) {
        int r = i >> 7, c = i & 127;
        g_hf[(row0 + r) * CELL + c] = Hs[r * HSST + c];
    }

    /* final chunk: write h, c tail of output */
    if (ci == NCHUNK - 1) {
        size_t baseH = (size_t)BSZ * TSZ * DOUT;
        size_t baseC = baseH + (size_t)BSZ * CELL;
        for (int i = tid; i < ROWS * CELL; i += NTHR) {
            int r = i >> 7, c = i & 127;
            out[baseH + (size_t)(row0 + r) * CELL + c] = Hs[r * HSST + c];
        }
#pragma unroll
        for (int mt = 0; mt < 2; mt++)
#pragma unroll
            for (int half = 0; half < 2; half++) {
                int r = mt * 16 + r0 + 8 * half;
                int cidx = mt * 4 + half * 2;
                *(float2*)&out[baseC + (size_t)(row0 + r) * CELL + cell0] =
                    make_float2(cst[cidx], cst[cidx + 1]);
            }
    }
}

/* ---------------- launch: 17 graph nodes ---------------- */
extern "C" void kernel_launch(void* const* d_in, const int* in_sizes, int n_in,
                              void* d_out, int out_size) {
    const float* inputs = (const float*)d_in[0];
    const float* We     = (const float*)d_in[1];
    const float* be     = (const float*)d_in[2];
    const float* W_ih   = (const float*)d_in[3];
    const float* W_hh   = (const float*)d_in[4];
    const float* b_ih   = (const float*)d_in[5];
    const float* b_hh   = (const float*)d_in[6];
    const float* Wo     = (const float*)d_in[7];
    const float* bo     = (const float*)d_in[8];
    float* out = (float*)d_out;

    static int smem_set = 0;
    if (!smem_set) {
        cudaFuncSetAttribute(lstm_chunk, cudaFuncAttributeMaxDynamicSharedMemorySize,
                             SMEM_BYTES);
        smem_set = 1;
    }

    setup_kernel<<<(BSZ * CELL + 255) / 256, 256>>>(W_ih, W_hh, b_ih, b_hh);
    for (int ci = 0; ci < NCHUNK; ci++) {
        prepass_kernel<<<512, NTHR>>>(inputs, We, be, ci);
        lstm_chunk<<<NCTA, NTHR, SMEM_BYTES>>>(Wo, bo, out, ci);
    }
}

// round 13
// speedup vs baseline: 1.1416x; 1.1416x over previous
#include <cuda_runtime.h>
#include <cuda_bf16.h>
#include <math.h>

#define BSZ   4096
#define TSZ   1024
#define DIN   2
#define EMD   128
#define CELL  128
#define DOUT  5
#define GATES 512
#define NCTA  128
#define ROWS  32
#define NTHR  512
#define STR   136            /* A-plane row stride (bf16): 4-bank offset/row, ldmatrix conflict-free */
#define WOST  132
#define NBF   (16*16*4*32*8) /* 512KB: [kt][w][nt][lane][hi x4 | lo x4] */
#define CHUNK 128
#define NCHUNK (TSZ / CHUNK)

typedef unsigned int u32;

/* ---------------- persistent device scratch ---------------- */
__device__ __nv_bfloat16 g_B[NBF];
__device__ float g_bias[GATES];
#define GF4 (128UL * NCTA * 8 * 512)   /* 1 GiB gates_e chunk: [t%128][ctab][j][tid] float4 */
__device__ float4 g_G[GF4];
__device__ float g_hf[BSZ * CELL];
__device__ float g_cf[BSZ * CELL];

__device__ __forceinline__ float4* gchunk(int t, int ctab) {
    return g_G + ((size_t)(t & (CHUNK - 1)) * NCTA + ctab) * 4096;
}

/* ---------------- helpers ---------------- */
__device__ __forceinline__ float sigm(float x) {
    return __fdividef(1.0f, 1.0f + __expf(-x));
}
__device__ __forceinline__ float tanh_f(float x) {
    float e = __expf(-2.0f * fabsf(x));
    float r = __fdividef(1.0f - e, 1.0f + e);
    return copysignf(r, x);
}
__device__ __forceinline__ void mma16816(float* d, const u32* a, u32 b0, u32 b1) {
    asm("mma.sync.aligned.m16n8k16.row.col.f32.bf16.bf16.f32 "
        "{%0,%1,%2,%3}, {%4,%5,%6,%7}, {%8,%9}, {%0,%1,%2,%3};"
        : "+f"(d[0]), "+f"(d[1]), "+f"(d[2]), "+f"(d[3])
        : "r"(a[0]), "r"(a[1]), "r"(a[2]), "r"(a[3]), "r"(b0), "r"(b1));
}
__device__ __forceinline__ void ldmat4(u32* r, u32 addr) {
    asm volatile("ldmatrix.sync.aligned.m8n8.x4.shared.b16 {%0,%1,%2,%3}, [%4];"
        : "=r"(r[0]), "=r"(r[1]), "=r"(r[2]), "=r"(r[3]) : "r"(addr));
}
__device__ __forceinline__ void cp16(void* s, const void* g) {
    unsigned sa = (unsigned)__cvta_generic_to_shared(s);
    asm volatile("cp.async.cg.shared.global [%0], [%1], 16;" :: "r"(sa), "l"(g));
}
__device__ __forceinline__ void cp_commit() { asm volatile("cp.async.commit_group;"); }
__device__ __forceinline__ void cp_wait0()  { asm volatile("cp.async.wait_group 0;" ::: "memory"); }

/* ---------------- setup ---------------- */
__global__ void setup_kernel(const float* __restrict__ W_ih, const float* __restrict__ W_hh,
                             const float* __restrict__ b_ih, const float* __restrict__ b_hh) {
    int idx = blockIdx.x * blockDim.x + threadIdx.x;
    if (idx < NBF) {
        int j  = idx & 3;
        int p  = (idx >> 2) & 1;
        int l  = (idx >> 3) & 31;
        int nt = (idx >> 8) & 3;
        int w  = (idx >> 10) & 15;
        int kt = idx >> 14;
        int k  = kt * 16 + 2 * (l & 3) + (j & 1) + 8 * (j >> 1);
        int n  = nt * 128 + 8 * w + (l >> 2);
        float v = (k < EMD) ? W_ih[n * EMD + k] : W_hh[n * CELL + (k - EMD)];
        __nv_bfloat16 hi = __float2bfloat16_rn(v);
        g_B[idx] = p ? __float2bfloat16_rn(v - __bfloat162float(hi)) : hi;
    }
    if (idx < GATES) g_bias[idx] = b_ih[idx] + b_hh[idx];
    if (idx < BSZ * CELL) { g_hf[idx] = 0.0f; g_cf[idx] = 0.0f; }
}

/* ================= pre-pass =================
 * grid 512: ctab = bx & 127, tc = bx >> 7 (32 timesteps/CTA).
 * B kt0-3 staged in smem once per CTA (halves L2 traffic); kt4-7 streamed.
 * Double-buffered e-planes -> 1 sync per timestep.
 * smem: Ae[2][hi/lo] 4x8704=34816 | xsh @34816 (8192) | WeS @43008 (1024)
 *       beS @44032 (512) | Bs @44544 (131072) -> 175616 bytes */
#define POFF_XSH 34816
#define POFF_WES 43008
#define POFF_BES 44032
#define POFF_BS  44544
#define SMEM_P   175616

__global__ void __launch_bounds__(NTHR, 1)
prepass_kernel(const float* __restrict__ inputs,
               const float* __restrict__ We, const float* __restrict__ be, int ci) {
    extern __shared__ char smc[];
    __nv_bfloat16* AeHi[2] = { (__nv_bfloat16*)smc,           (__nv_bfloat16*)(smc + 17408) };
    __nv_bfloat16* AeLo[2] = { (__nv_bfloat16*)(smc + 8704),  (__nv_bfloat16*)(smc + 26112) };
    float2* xsh = (float2*)(smc + POFF_XSH);
    float*  WeS = (float*)(smc + POFF_WES);
    float*  beS = (float*)(smc + POFF_BES);
    const uint4* BsU4 = (const uint4*)(smc + POFF_BS);

    const int tid  = threadIdx.x;
    const int ctab = blockIdx.x & 127;
    const int tc   = blockIdx.x >> 7;
    const int row0 = ctab * ROWS;
    const int t0   = ci * CHUNK + tc * 32;
    const int w    = tid >> 5;
    const int l    = tid & 31;

    /* stage B kt0-3 (contiguous first 8192 uint4 of g_B) */
    {
        uint4* dst = (uint4*)(smc + POFF_BS);
        const uint4* src = (const uint4*)g_B;
#pragma unroll
        for (int i = 0; i < 16; i++) cp16(dst + tid + i * 512, src + tid + i * 512);
        cp_commit();
    }
    for (int i = tid; i < EMD; i += NTHR) {
        WeS[2 * i] = We[2 * i]; WeS[2 * i + 1] = We[2 * i + 1]; beS[i] = be[i];
    }
    for (int i = tid; i < ROWS * 32; i += NTHR) {
        int r = i >> 5, tt = i & 31;
        xsh[i] = ((const float2*)inputs)[(size_t)(row0 + r) * TSZ + t0 + tt];
    }

    float bia[4][2];
    {
        const int cq = l & 3, cell0 = 8 * w + 2 * cq;
#pragma unroll
        for (int nt = 0; nt < 4; nt++) {
            bia[nt][0] = g_bias[nt * 128 + cell0];
            bia[nt][1] = g_bias[nt * 128 + cell0 + 1];
        }
    }

    const int rl = (l & 7) + ((l >> 3) & 1) * 8;
    const int kl = (l >> 4) * 8;
    const u32 sb = (u32)__cvta_generic_to_shared(smc);
    const u32 aoff = (u32)((rl * STR + kl) * 2);
    const u32 hiB[2] = { sb + 0 + aoff, sb + 17408 + aoff };
    const u32 loB[2] = { sb + 8704 + aoff, sb + 26112 + aoff };

    const int ej  = tid >> 2;
    const int er0 = (tid & 3) * 8;
    const uint4* Bp = (const uint4*)g_B;
    const u32 bbase = w * 128 + l;

    cp_wait0();
    __syncthreads();

    /* e(0) into buf 0 */
    {
        float w0 = WeS[2 * ej], w1 = WeS[2 * ej + 1], bj = beS[ej];
#pragma unroll
        for (int i = 0; i < 8; i++) {
            int r = er0 + i;
            float2 x = xsh[r * 32];
            float e = fmaxf(fmaf(w0, x.x, fmaf(w1, x.y, bj)), 0.0f);
            __nv_bfloat16 hi = __float2bfloat16_rn(e);
            AeHi[0][r * STR + ej] = hi;
            AeLo[0][r * STR + ej] = __float2bfloat16_rn(e - __bfloat162float(hi));
        }
    }
    __syncthreads();

    for (int tt = 0; tt < 32; tt++) {
        const int par = tt & 1;
        float D[2][4][4];
#pragma unroll
        for (int mt = 0; mt < 2; mt++)
#pragma unroll
            for (int nt = 0; nt < 4; nt++) {
                D[mt][nt][0] = bia[nt][0]; D[mt][nt][1] = bia[nt][1];
                D[mt][nt][2] = bia[nt][0]; D[mt][nt][3] = bia[nt][1];
            }

        uint4 Bb[2][4];
#pragma unroll
        for (int kt = 0; kt < 8; kt++) {
            if (kt >= 3 && kt < 7) {   /* prefetch streamed kt+1 (kt 4..7) */
#pragma unroll
                for (int nt = 0; nt < 4; nt++)
                    Bb[(kt + 1) & 1][nt] = __ldg(Bp + (kt + 1) * 2048 + bbase + nt * 32);
            }
            uint4 Bf[4];
            if (kt < 4) {
#pragma unroll
                for (int nt = 0; nt < 4; nt++)
                    Bf[nt] = BsU4[kt * 2048 + bbase + nt * 32];
            } else {
#pragma unroll
                for (int nt = 0; nt < 4; nt++) Bf[nt] = Bb[kt & 1][nt];
            }
#pragma unroll
            for (int mt = 0; mt < 2; mt++) {
                u32 Ah[4], Al[4];
                ldmat4(Ah, hiB[par] + kt * 32 + mt * (16 * STR * 2));
                ldmat4(Al, loB[par] + kt * 32 + mt * (16 * STR * 2));
#pragma unroll
                for (int nt = 0; nt < 4; nt++) mma16816(D[mt][nt], Ah, Bf[nt].x, Bf[nt].y);
#pragma unroll
                for (int nt = 0; nt < 4; nt++) mma16816(D[mt][nt], Ah, Bf[nt].z, Bf[nt].w);
#pragma unroll
                for (int nt = 0; nt < 4; nt++) mma16816(D[mt][nt], Al, Bf[nt].x, Bf[nt].y);
            }
        }

        /* store D in per-thread fragment order */
        float4* gp = gchunk(t0 + tt, ctab) + tid;
#pragma unroll
        for (int mt = 0; mt < 2; mt++)
#pragma unroll
            for (int nt = 0; nt < 4; nt++)
                gp[(mt * 4 + nt) * 512] =
                    make_float4(D[mt][nt][0], D[mt][nt][1], D[mt][nt][2], D[mt][nt][3]);

        /* e(tt+1) into alternate buffer (overlaps other warps' GEMM) */
        if (tt < 31) {
            float w0 = WeS[2 * ej], w1 = WeS[2 * ej + 1], bj = beS[ej];
            const int nb = par ^ 1;
#pragma unroll
            for (int i = 0; i < 8; i++) {
                int r = er0 + i;
                float2 x = xsh[r * 32 + tt + 1];
                float e = fmaxf(fmaf(w0, x.x, fmaf(w1, x.y, bj)), 0.0f);
                __nv_bfloat16 hi = __float2bfloat16_rn(e);
                AeHi[nb][r * STR + ej] = hi;
                AeLo[nb][r * STR + ej] = __float2bfloat16_rn(e - __bfloat162float(hi));
            }
        }
        __syncthreads();
    }
}

/* ================= recurrent chunk kernel =================
 * Double-buffered h planes -> 1 sync/step; single G buffer (thread-private refill);
 * B kt8-10 staged in smem, kt11-15 streamed.
 * smem: P[2][hi/lo] 4x8704=34816 | WoS @34816 (2640) | Gs @37456 (65536)
 *       Bs @102992 (98304) -> 201296 bytes */
#define LOFF_WOS 34816
#define LOFF_GS  37456
#define LOFF_BS  102992
#define SMEM_L   201296

__global__ void __launch_bounds__(NTHR, 1)
lstm_chunk(const float* __restrict__ Wo, const float* __restrict__ bov,
           float* __restrict__ out, int ci) {
    extern __shared__ char smc[];
    __nv_bfloat16* PHi[2] = { (__nv_bfloat16*)smc,           (__nv_bfloat16*)(smc + 17408) };
    __nv_bfloat16* PLo[2] = { (__nv_bfloat16*)(smc + 8704),  (__nv_bfloat16*)(smc + 26112) };
    float*  WoS = (float*)(smc + LOFF_WOS);
    float4* GsF4 = (float4*)(smc + LOFF_GS);
    const uint4* BsU4 = (const uint4*)(smc + LOFF_BS);

    const int tid  = threadIdx.x;
    const int ctab = blockIdx.x;
    const int row0 = ctab * ROWS;
    const int w    = tid >> 5;
    const int l    = tid & 31;
    const int r0   = l >> 2;
    const int cq   = l & 3;
    const int cell0 = 8 * w + 2 * cq;

    const int rl = (l & 7) + ((l >> 3) & 1) * 8;
    const int kl = (l >> 4) * 8;
    const u32 sb = (u32)__cvta_generic_to_shared(smc);
    const u32 aoff = (u32)((rl * STR + kl) * 2);
    const u32 hiB[2] = { sb + 0 + aoff, sb + 17408 + aoff };
    const u32 loB[2] = { sb + 8704 + aoff, sb + 26112 + aoff };

    /* stage B kt8-10 (6144 uint4 starting at uint4 index 8*2048) */
    {
        uint4* dst = (uint4*)(smc + LOFF_BS);
        const uint4* src = (const uint4*)g_B + 8 * 2048;
#pragma unroll
        for (int i = 0; i < 12; i++) cp16(dst + tid + i * 512, src + tid + i * 512);
        cp_commit();
    }
    for (int i = tid; i < DOUT * CELL; i += NTHR) WoS[(i / CELL) * WOST + (i % CELL)] = Wo[i];
    /* rebuild h planes (into plane 1: step tt=0 reads parity^1 = 1) */
    for (int i = tid; i < ROWS * CELL; i += NTHR) {
        int r = i >> 7, c = i & 127;
        float h = g_hf[(row0 + r) * CELL + c];
        __nv_bfloat16 hb = __float2bfloat16_rn(h);
        PHi[1][r * STR + c] = hb;
        PLo[1][r * STR + c] = __float2bfloat16_rn(h - __bfloat162float(hb));
    }
    float cst[8];
#pragma unroll
    for (int mt = 0; mt < 2; mt++)
#pragma unroll
        for (int half = 0; half < 2; half++) {
            int r = mt * 16 + r0 + 8 * half;
            cst[mt * 4 + half * 2]     = g_cf[(row0 + r) * CELL + cell0];
            cst[mt * 4 + half * 2 + 1] = g_cf[(row0 + r) * CELL + cell0 + 1];
        }

    const float bo_r = (tid < ROWS * DOUT * 2) ? bov[(tid % 10) >> 1] : 0.0f;
    const uint4* Bp = (const uint4*)g_B;
    const u32 bbase = w * 128 + l;

    /* G(first) into Gs (thread-private addresses) */
    {
        const float4* src = gchunk(ci * CHUNK, ctab);
#pragma unroll
        for (int i = 0; i < 8; i++) cp16(GsF4 + tid + i * 512, src + tid + i * 512);
        cp_commit();
    }
    cp_wait0();
    __syncthreads();

    float hv[8];
    for (int tt = 0; tt < CHUNK; tt++) {
        const int t = ci * CHUNK + tt;
        const int par = tt & 1;

        /* D init from own Gs slots, then refill same slots with G(t+1) */
        float D[2][4][4];
#pragma unroll
        for (int mt = 0; mt < 2; mt++)
#pragma unroll
            for (int nt = 0; nt < 4; nt++) {
                float4 v = GsF4[(mt * 4 + nt) * 512 + tid];
                D[mt][nt][0] = v.x; D[mt][nt][1] = v.y;
                D[mt][nt][2] = v.z; D[mt][nt][3] = v.w;
            }
        if (tt < CHUNK - 1) {
            const float4* src = gchunk(t + 1, ctab);
#pragma unroll
            for (int i = 0; i < 8; i++) cp16(GsF4 + tid + i * 512, src + tid + i * 512);
            cp_commit();
        }

        /* recurrent GEMM: K=128 from h plane[par^1] */
        uint4 Bb[2][4];
#pragma unroll
        for (int kt = 0; kt < 8; kt++) {
            if (kt >= 2 && kt < 7) {   /* prefetch streamed kt+1 (kt 3..7 -> global kt+9..15) */
#pragma unroll
                for (int nt = 0; nt < 4; nt++)
                    Bb[(kt + 1) & 1][nt] = __ldg(Bp + (kt + 9) * 2048 + bbase + nt * 32);
            }
            uint4 Bf[4];
            if (kt < 3) {
#pragma unroll
                for (int nt = 0; nt < 4; nt++)
                    Bf[nt] = BsU4[kt * 2048 + bbase + nt * 32];
            } else {
#pragma unroll
                for (int nt = 0; nt < 4; nt++) Bf[nt] = Bb[kt & 1][nt];
            }
#pragma unroll
            for (int mt = 0; mt < 2; mt++) {
                u32 Ah[4], Al[4];
                ldmat4(Ah, hiB[par ^ 1] + kt * 32 + mt * (16 * STR * 2));
                ldmat4(Al, loB[par ^ 1] + kt * 32 + mt * (16 * STR * 2));
#pragma unroll
                for (int nt = 0; nt < 4; nt++) mma16816(D[mt][nt], Ah, Bf[nt].x, Bf[nt].y);
#pragma unroll
                for (int nt = 0; nt < 4; nt++) mma16816(D[mt][nt], Ah, Bf[nt].z, Bf[nt].w);
#pragma unroll
                for (int nt = 0; nt < 4; nt++) mma16816(D[mt][nt], Al, Bf[nt].x, Bf[nt].y);
            }
        }

        /* pointwise */
#pragma unroll
        for (int mt = 0; mt < 2; mt++)
#pragma unroll
            for (int half = 0; half < 2; half++)
#pragma unroll
                for (int cc = 0; cc < 2; cc++) {
                    const int e = 2 * half + cc;
                    float iv = sigm(D[mt][0][e]);
                    float fv = sigm(D[mt][1][e]);
                    float gv = tanh_f(D[mt][2][e]);
                    float ov = sigm(D[mt][3][e]);
                    const int cidx = mt * 4 + half * 2 + cc;
                    cst[cidx] = fmaf(fv, cst[cidx], iv * gv);
                    hv[cidx] = ov * tanh_f(cst[cidx]);
                }

        /* write h into plane[par] (other buffer than the one GEMM read) */
#pragma unroll
        for (int mt = 0; mt < 2; mt++)
#pragma unroll
            for (int half = 0; half < 2; half++) {
                const int r = mt * 16 + r0 + 8 * half;
                const int cidx = mt * 4 + half * 2;
                float h0 = hv[cidx], h1 = hv[cidx + 1];
                __nv_bfloat16 b0 = __float2bfloat16_rn(h0);
                __nv_bfloat16 b1 = __float2bfloat16_rn(h1);
                *(__nv_bfloat162*)&PHi[par][r * STR + cell0] = __nv_bfloat162(b0, b1);
                *(__nv_bfloat162*)&PLo[par][r * STR + cell0] = __nv_bfloat162(
                    __float2bfloat16_rn(h0 - __bfloat162float(b0)),
                    __float2bfloat16_rn(h1 - __bfloat162float(b1)));
            }

        cp_wait0();        /* own G(t+1) slots filled */
        __syncthreads();   /* everyone's h(t) + G(t+1) visible */

        /* y-phase: reads plane[par]; overlaps next step (race-free: next write
         * targets plane[par^1]; plane[par] rewritten only after next sync) */
        if (tid < ROWS * DOUT * 2) {
            int r = tid / 10, q = tid % 10;
            int d = q >> 1, half = q & 1;
            const __nv_bfloat16* ph = PHi[par] + r * STR + 64 * half;
            const __nv_bfloat16* pl = PLo[par] + r * STR + 64 * half;
            const float* wrow = WoS + d * WOST + 64 * half;
            float s = 0.0f;
#pragma unroll 16
            for (int j = 0; j < 64; j++) {
                float h = __bfloat162float(ph[j]) + __bfloat162float(pl[j]);
                s = fmaf(h, wrow[j], s);
            }
            s += __shfl_xor_sync(0xffffffffu, s, 1);
            if (!half)
                out[((size_t)(row0 + r) * TSZ + t) * DOUT + d] = s + bo_r;
        }
    }

    /* epilogue: persist h (reconstructed from plane 1: last tt=127 is odd) and c */
#pragma unroll
    for (int mt = 0; mt < 2; mt++)
#pragma unroll
        for (int half = 0; half < 2; half++) {
            int r = mt * 16 + r0 + 8 * half;
            int cidx = mt * 4 + half * 2;
            *(float2*)&g_cf[(row0 + r) * CELL + cell0] = make_float2(cst[cidx], cst[cidx + 1]);
        }
    for (int i = tid; i < ROWS * CELL; i += NTHR) {
        int r = i >> 7, c = i & 127;
        g_hf[(row0 + r) * CELL + c] =
            __bfloat162float(PHi[1][r * STR + c]) + __bfloat162float(PLo[1][r * STR + c]);
    }

    if (ci == NCHUNK - 1) {
        size_t baseH = (size_t)BSZ * TSZ * DOUT;
        size_t baseC = baseH + (size_t)BSZ * CELL;
        for (int i = tid; i < ROWS * CELL; i += NTHR) {
            int r = i >> 7, c = i & 127;
            out[baseH + (size_t)(row0 + r) * CELL + c] =
                __bfloat162float(PHi[1][r * STR + c]) + __bfloat162float(PLo[1][r * STR + c]);
        }
#pragma unroll
        for (int mt = 0; mt < 2; mt++)
#pragma unroll
            for (int half = 0; half < 2; half++) {
                int r = mt * 16 + r0 + 8 * half;
                int cidx = mt * 4 + half * 2;
                *(float2*)&out[baseC + (size_t)(row0 + r) * CELL + cell0] =
                    make_float2(cst[cidx], cst[cidx + 1]);
            }
    }
}

/* ---------------- launch: 17 graph nodes ---------------- */
extern "C" void kernel_launch(void* const* d_in, const int* in_sizes, int n_in,
                              void* d_out, int out_size) {
    const float* inputs = (const float*)d_in[0];
    const float* We     = (const float*)d_in[1];
    const float* be     = (const float*)d_in[2];
    const float* W_ih   = (const float*)d_in[3];
    const float* W_hh   = (const float*)d_in[4];
    const float* b_ih   = (const float*)d_in[5];
    const float* b_hh   = (const float*)d_in[6];
    const float* Wo     = (const float*)d_in[7];
    const float* bo     = (const float*)d_in[8];
    float* out = (float*)d_out;

    static int smem_set = 0;
    if (!smem_set) {
        cudaFuncSetAttribute(prepass_kernel, cudaFuncAttributeMaxDynamicSharedMemorySize, SMEM_P);
        cudaFuncSetAttribute(lstm_chunk, cudaFuncAttributeMaxDynamicSharedMemorySize, SMEM_L);
        smem_set = 1;
    }

    setup_kernel<<<(BSZ * CELL + 255) / 256, 256>>>(W_ih, W_hh, b_ih, b_hh);
    for (int ci = 0; ci < NCHUNK; ci++) {
        prepass_kernel<<<512, NTHR, SMEM_P>>>(inputs, We, be, ci);
        lstm_chunk<<<NCTA, NTHR, SMEM_L>>>(Wo, bo, out, ci);
    }
}

// round 15
// speedup vs baseline: 1.6917x; 1.4818x over previous
#include <cuda_runtime.h>
#include <cuda_fp16.h>
#include <math.h>

#define BSZ   4096
#define TSZ   1024
#define DIN   2
#define EMD   128
#define CELL  128
#define DOUT  5
#define GATES 512
#define NCTA  128
#define ROWS  32
#define NTHR  512
#define STR   136             /* A-plane row stride (halfs): ldmatrix conflict-free */
#define WOST  132
#define NBF16 (16*16*4*32*4)  /* 131072 halfs = 256 KB: [kt][w][nt][lane][4] single fp16 */

typedef unsigned int u32;

/* ---------------- persistent device scratch ---------------- */
__device__ __half g_B[NBF16];
__device__ float  g_bias[GATES];

/* ---------------- helpers ---------------- */
__device__ __forceinline__ float sigm(float x) {
    return __fdividef(1.0f, 1.0f + __expf(-x));
}
__device__ __forceinline__ float tanh_f(float x) {
    float e = __expf(-2.0f * fabsf(x));
    float r = __fdividef(1.0f - e, 1.0f + e);
    return copysignf(r, x);
}
__device__ __forceinline__ void mma16816(float* d, const u32* a, u32 b0, u32 b1) {
    asm("mma.sync.aligned.m16n8k16.row.col.f32.f16.f16.f32 "
        "{%0,%1,%2,%3}, {%4,%5,%6,%7}, {%8,%9}, {%0,%1,%2,%3};"
        : "+f"(d[0]), "+f"(d[1]), "+f"(d[2]), "+f"(d[3])
        : "r"(a[0]), "r"(a[1]), "r"(a[2]), "r"(a[3]), "r"(b0), "r"(b1));
}
__device__ __forceinline__ void ldmat4(u32* r, u32 addr) {
    asm volatile("ldmatrix.sync.aligned.m8n8.x4.shared.b16 {%0,%1,%2,%3}, [%4];"
        : "=r"(r[0]), "=r"(r[1]), "=r"(r[2]), "=r"(r[3]) : "r"(addr));
}
__device__ __forceinline__ void cp16(void* s, const void* g) {
    unsigned sa = (unsigned)__cvta_generic_to_shared(s);
    asm volatile("cp.async.cg.shared.global [%0], [%1], 16;" :: "r"(sa), "l"(g));
}
__device__ __forceinline__ void cp_commit() { asm volatile("cp.async.commit_group;"); }
__device__ __forceinline__ void cp_wait0()  { asm volatile("cp.async.wait_group 0;" ::: "memory"); }

/* ---------------- setup: fp16 weights into mma B fragments ----------------
 * idx = (((kt*16 + w)*4 + nt)*32 + l)*4 + j
 * k = kt*16 + 2*(l&3) + (j&1) + 8*(j>>1);  n = nt*128 + 8*w + (l>>2). */
__global__ void setup_kernel(const float* __restrict__ W_ih, const float* __restrict__ W_hh,
                             const float* __restrict__ b_ih, const float* __restrict__ b_hh) {
    int idx = blockIdx.x * blockDim.x + threadIdx.x;
    if (idx < NBF16) {
        int j  = idx & 3;
        int l  = (idx >> 2) & 31;
        int nt = (idx >> 7) & 3;
        int w  = (idx >> 9) & 15;
        int kt = idx >> 13;
        int k  = kt * 16 + 2 * (l & 3) + (j & 1) + 8 * (j >> 1);
        int n  = nt * 128 + 8 * w + (l >> 2);
        float v = (k < EMD) ? W_ih[n * EMD + k] : W_hh[n * CELL + (k - EMD)];
        g_B[idx] = __float2half_rn(v);
    }
    if (idx < GATES) g_bias[idx] = b_ih[idx] + b_hh[idx];
}

/* ---------------- monolithic persistent kernel ----------------
 * 128 CTAs x 512 thr; CTA owns 32 batch rows for the whole sequence.
 * GEMM K=256: A = fp16 hi+lo planes (e | h), B = single fp16 -> 2 mma terms.
 * 1 sync/step (double-buffered e and h planes).
 * smem (bytes):
 *   E planes: [par][hi,lo]  0 / 8704 / 17408 / 26112
 *   H planes: [par][hi,lo]  34816 / 43520 / 52224 / 60928
 *   WoS 69632 (2640) | WeS 72272 (1024) | beS 73296 (512) | xs 73808 (512)
 *   Bs  74320 (+ 9*16384 = 147456) -> 221776 total */
#define OFF_EHI0 0
#define OFF_ELO0 8704
#define OFF_EHI1 17408
#define OFF_ELO1 26112
#define OFF_HHI0 34816
#define OFF_HLO0 43520
#define OFF_HHI1 52224
#define OFF_HLO1 60928
#define OFF_WOS  69632
#define OFF_WES  72272
#define OFF_BES  73296
#define OFF_XS   73808
#define OFF_BS   74320
#define NSTAGE   9            /* k-tiles staged in smem */
#define SMEM_BYTES (OFF_BS + NSTAGE * 16384)

__global__ void __launch_bounds__(NTHR, 1)
lstm_persist(const float* __restrict__ inputs,
             const float* __restrict__ We,  const float* __restrict__ be,
             const float* __restrict__ Wo,  const float* __restrict__ bov,
             float* __restrict__ out) {
    extern __shared__ char smc[];
    __half* EHi[2] = { (__half*)(smc + OFF_EHI0), (__half*)(smc + OFF_EHI1) };
    __half* ELo[2] = { (__half*)(smc + OFF_ELO0), (__half*)(smc + OFF_ELO1) };
    __half* HHi[2] = { (__half*)(smc + OFF_HHI0), (__half*)(smc + OFF_HHI1) };
    __half* HLo[2] = { (__half*)(smc + OFF_HLO0), (__half*)(smc + OFF_HLO1) };
    float*  WoS = (float*)(smc + OFF_WOS);
    float*  WeS = (float*)(smc + OFF_WES);
    float*  beS = (float*)(smc + OFF_BES);
    float2* xs  = (float2*)(smc + OFF_XS);       /* [2][32] */
    const uint2* BsU2 = (const uint2*)(smc + OFF_BS);

    const int tid  = threadIdx.x;
    const int row0 = blockIdx.x * ROWS;
    const int w    = tid >> 5;
    const int l    = tid & 31;
    const int r0   = l >> 2;
    const int cq   = l & 3;
    const int cell0 = 8 * w + 2 * cq;

    /* ldmatrix lane offsets (bytes within a plane) */
    const int rl = (l & 7) + ((l >> 3) & 1) * 8;
    const int kl = (l >> 4) * 8;
    const u32 sb = (u32)__cvta_generic_to_shared(smc);
    const u32 aoff = (u32)((rl * STR + kl) * 2);
    const u32 eB[2][2] = { { sb + OFF_EHI0 + aoff, sb + OFF_ELO0 + aoff },
                           { sb + OFF_EHI1 + aoff, sb + OFF_ELO1 + aoff } };
    const u32 hB[2][2] = { { sb + OFF_HHI0 + aoff, sb + OFF_HLO0 + aoff },
                           { sb + OFF_HHI1 + aoff, sb + OFF_HLO1 + aoff } };

    /* stage B kt0-8 into smem (9216 float4) */
    {
        float4* dst = (float4*)(smc + OFF_BS);
        const float4* src = (const float4*)g_B;
#pragma unroll
        for (int i = 0; i < 18; i++) cp16(dst + tid + i * NTHR, src + tid + i * NTHR);
        cp_commit();
    }
    /* small weights */
    for (int i = tid; i < DOUT * CELL; i += NTHR) WoS[(i / CELL) * WOST + (i % CELL)] = Wo[i];
    for (int i = tid; i < EMD; i += NTHR) {
        WeS[2 * i] = We[2 * i]; WeS[2 * i + 1] = We[2 * i + 1]; beS[i] = be[i];
    }
    /* zero h planes[1] (step 0 reads par^1 = 1) */
    for (int i = tid; i < ROWS * STR; i += NTHR) {
        HHi[1][i] = __float2half_rn(0.0f);
        HLo[1][i] = __float2half_rn(0.0f);
    }
    /* stage x(1) into xs[1] */
    if (tid < ROWS)
        xs[ROWS + tid] = ((const float2*)inputs)[(size_t)(row0 + tid) * TSZ + 1];

    /* gate biases */
    float bia[4][2];
#pragma unroll
    for (int nt = 0; nt < 4; nt++) {
        bia[nt][0] = g_bias[nt * 128 + cell0];
        bia[nt][1] = g_bias[nt * 128 + cell0 + 1];
    }
    float cst[8], hv[8];
#pragma unroll
    for (int i = 0; i < 8; i++) cst[i] = 0.0f;

    const float bo_r = (tid < ROWS * DOUT * 2) ? bov[(tid % 10) >> 1] : 0.0f;
    const int ej  = tid >> 2;
    const int er0 = (tid & 3) * 8;

    cp_wait0();
    __syncthreads();

    /* e(0) into E[0] (x(0) read straight from global) */
    {
        float w0 = WeS[2 * ej], w1 = WeS[2 * ej + 1], bj = beS[ej];
#pragma unroll
        for (int i = 0; i < 8; i++) {
            int r = er0 + i;
            float2 x = ((const float2*)inputs)[(size_t)(row0 + r) * TSZ];
            float e = fmaxf(fmaf(w0, x.x, fmaf(w1, x.y, bj)), 0.0f);
            __half hi = __float2half_rn(e);
            EHi[0][r * STR + ej] = hi;
            ELo[0][r * STR + ej] = __float2half_rn(e - __half2float(hi));
        }
    }
    __syncthreads();

    const uint2* Bp = (const uint2*)g_B;       /* idx: kt*2048 + w*128 + nt*32 + l */
    const u32 bbase = w * 128 + l;

    for (int t = 0; t < TSZ; t++) {
        const int par = t & 1;

        float D[2][4][4];
#pragma unroll
        for (int mt = 0; mt < 2; mt++)
#pragma unroll
            for (int nt = 0; nt < 4; nt++) {
                D[mt][nt][0] = bia[nt][0]; D[mt][nt][1] = bia[nt][1];
                D[mt][nt][2] = bia[nt][0]; D[mt][nt][3] = bia[nt][1];
            }

        /* streamed-B ring: kt 9..15, prefetch distance 2 */
        uint2 Bb[2][4];
#pragma unroll
        for (int nt = 0; nt < 4; nt++) Bb[0][nt] = __ldg(Bp +  9 * 2048 + bbase + nt * 32);
#pragma unroll
        for (int nt = 0; nt < 4; nt++) Bb[1][nt] = __ldg(Bp + 10 * 2048 + bbase + nt * 32);

#pragma unroll
        for (int kt = 0; kt < 16; kt++) {
            uint2 Bf[4];
            if (kt < NSTAGE) {
#pragma unroll
                for (int nt = 0; nt < 4; nt++)
                    Bf[nt] = BsU2[kt * 2048 + bbase + nt * 32];
            } else {
#pragma unroll
                for (int nt = 0; nt < 4; nt++) Bf[nt] = Bb[(kt - 9) & 1][nt];
                if (kt >= 9 && kt <= 13) {
#pragma unroll
                    for (int nt = 0; nt < 4; nt++)
                        Bb[(kt - 9) & 1][nt] = __ldg(Bp + (kt + 2) * 2048 + bbase + nt * 32);
                }
            }
            const u32 hiA = (kt < 8) ? (eB[par][0] + kt * 32) : (hB[par ^ 1][0] + (kt - 8) * 32);
            const u32 loA = (kt < 8) ? (eB[par][1] + kt * 32) : (hB[par ^ 1][1] + (kt - 8) * 32);
#pragma unroll
            for (int mt = 0; mt < 2; mt++) {
                u32 Ah[4], Al[4];
                ldmat4(Ah, hiA + mt * (16 * STR * 2));
                ldmat4(Al, loA + mt * (16 * STR * 2));
#pragma unroll
                for (int nt = 0; nt < 4; nt++) mma16816(D[mt][nt], Ah, Bf[nt].x, Bf[nt].y);
#pragma unroll
                for (int nt = 0; nt < 4; nt++) mma16816(D[mt][nt], Al, Bf[nt].x, Bf[nt].y);
            }
        }

        /* pointwise */
#pragma unroll
        for (int mt = 0; mt < 2; mt++)
#pragma unroll
            for (int half = 0; half < 2; half++)
#pragma unroll
                for (int cc = 0; cc < 2; cc++) {
                    const int e = 2 * half + cc;
                    float iv = sigm(D[mt][0][e]);
                    float fv = sigm(D[mt][1][e]);
                    float gv = tanh_f(D[mt][2][e]);
                    float ov = sigm(D[mt][3][e]);
                    const int ci = mt * 4 + half * 2 + cc;
                    cst[ci] = fmaf(fv, cst[ci], iv * gv);
                    hv[ci] = ov * tanh_f(cst[ci]);
                }

        /* write h(t) into H[par] (read next step + by y-phase) */
#pragma unroll
        for (int mt = 0; mt < 2; mt++)
#pragma unroll
            for (int half = 0; half < 2; half++) {
                const int r = mt * 16 + r0 + 8 * half;
                const int ci = mt * 4 + half * 2;
                float h0 = hv[ci], h1 = hv[ci + 1];
                __half b0 = __float2half_rn(h0);
                __half b1 = __float2half_rn(h1);
                *(__half2*)&HHi[par][r * STR + cell0] = __halves2half2(b0, b1);
                *(__half2*)&HLo[par][r * STR + cell0] = __halves2half2(
                    __float2half_rn(h0 - __half2float(b0)),
                    __float2half_rn(h1 - __half2float(b1)));
            }

        /* e(t+1) into E[par^1] (xs[(t+1)&1] staged at step t-1 / prologue) */
        if (t < TSZ - 1) {
            float w0 = WeS[2 * ej], w1 = WeS[2 * ej + 1], bj = beS[ej];
            const float2* xp = xs + (par ^ 1) * ROWS;
#pragma unroll
            for (int i = 0; i < 8; i++) {
                int r = er0 + i;
                float2 x = xp[r];
                float e = fmaxf(fmaf(w0, x.x, fmaf(w1, x.y, bj)), 0.0f);
                __half hi = __float2half_rn(e);
                EHi[par ^ 1][r * STR + ej] = hi;
                ELo[par ^ 1][r * STR + ej] = __float2half_rn(e - __half2float(hi));
            }
        }
        /* stage x(t+2) into xs[par] (consumed at step t+1, after this sync) */
        if (t < TSZ - 2 && tid < ROWS)
            xs[par * ROWS + tid] =
                ((const float2*)inputs)[(size_t)(row0 + tid) * TSZ + t + 2];

        __syncthreads();

        /* y-phase: reads H[par] (hi+lo) */
        if (tid < ROWS * DOUT * 2) {
            int r = tid / 10, q = tid % 10;
            int d = q >> 1, half = q & 1;
            const __half* ph = HHi[par] + r * STR + 64 * half;
            const __half* pl = HLo[par] + r * STR + 64 * half;
            const float* wrow = WoS + d * WOST + 64 * half;
            float s = 0.0f;
#pragma unroll 16
            for (int j = 0; j < 64; j++) {
                float h = __half2float(ph[j]) + __half2float(pl[j]);
                s = fmaf(h, wrow[j], s);
            }
            s += __shfl_xor_sync(0xffffffffu, s, 1);
            if (!half)
                out[((size_t)(row0 + r) * TSZ + t) * DOUT + d] = s + bo_r;
        }
    }

    /* tail: final h from H[1] (t=1023 odd), c from regs */
    size_t baseH = (size_t)BSZ * TSZ * DOUT;
    size_t baseC = baseH + (size_t)BSZ * CELL;
    for (int i = tid; i < ROWS * CELL; i += NTHR) {
        int r = i >> 7, c = i & 127;
        out[baseH + (size_t)(row0 + r) * CELL + c] =
            __half2float(HHi[1][r * STR + c]) + __half2float(HLo[1][r * STR + c]);
    }
#pragma unroll
    for (int mt = 0; mt < 2; mt++)
#pragma unroll
        for (int half = 0; half < 2; half++) {
            int r = mt * 16 + r0 + 8 * half;
            int ci = mt * 4 + half * 2;
            *(float2*)&out[baseC + (size_t)(row0 + r) * CELL + cell0] =
                make_float2(cst[ci], cst[ci + 1]);
        }
}

/* ---------------- launch: 2 graph nodes ---------------- */
extern "C" void kernel_launch(void* const* d_in, const int* in_sizes, int n_in,
                              void* d_out, int out_size) {
    const float* inputs = (const float*)d_in[0];
    const float* We     = (const float*)d_in[1];
    const float* be     = (const float*)d_in[2];
    const float* W_ih   = (const float*)d_in[3];
    const float* W_hh   = (const float*)d_in[4];
    const float* b_ih   = (const float*)d_in[5];
    const float* b_hh   = (const float*)d_in[6];
    const float* Wo     = (const float*)d_in[7];
    const float* bo     = (const float*)d_in[8];
    float* out = (float*)d_out;

    static int smem_set = 0;
    if (!smem_set) {
        cudaFuncSetAttribute(lstm_persist, cudaFuncAttributeMaxDynamicSharedMemorySize,
                             SMEM_BYTES);
        smem_set = 1;
    }

    setup_kernel<<<(NBF16 + 255) / 256, 256>>>(W_ih, W_hh, b_ih, b_hh);
    lstm_persist<<<NCTA, NTHR, SMEM_BYTES>>>(inputs, We, be, Wo, bo, out);
}